// round 2
// baseline (speedup 1.0000x reference)
#include <cuda_runtime.h>

typedef unsigned long long u64;

#define NTHREADS 128
#define NBLOCKS  (148 * 3)

// ---------------- packed f32x2 helpers (sm_103a) ----------------
__device__ __forceinline__ u64 fma2(u64 a, u64 b, u64 c) {
    u64 d;
    asm("fma.rn.f32x2 %0, %1, %2, %3;" : "=l"(d) : "l"(a), "l"(b), "l"(c));
    return d;
}
__device__ __forceinline__ u64 pack2(float lo, float hi) {
    u64 d;
    asm("mov.b64 %0, {%1, %2};" : "=l"(d) : "f"(lo), "f"(hi));
    return d;
}
__device__ __forceinline__ void unpack2(u64 v, float& lo, float& hi) {
    asm("mov.b64 {%0, %1}, %2;" : "=f"(lo), "=f"(hi) : "l"(v));
}
__device__ __forceinline__ u64 bcast(float x) { return pack2(x, x); }
__device__ __forceinline__ u64 lds64(const float* p) {
    return *reinterpret_cast<const u64*>(p);
}
__device__ __forceinline__ ulonglong2 lds128(const float* p) {
    return *reinterpret_cast<const ulonglong2*>(p);
}

// ---------------- fast activations (accurate to ~1e-6 rel) ----------------
__device__ __forceinline__ float sigf(float x) {
    float e = __expf(-x);
    return __fdividef(1.0f, 1.0f + e);
}
__device__ __forceinline__ float tanhfast(float x) {
    float e = __expf(-2.0f * x);
    return __fdividef(2.0f, 1.0f + e) - 1.0f;
}

// SMEM layout (floats): all offsets 16B-aligned where float4 loads occur
#define OFF_W2T   0        // 64*128 = 8192, layout [j][k]: row j holds (W2[k][j]) for k=0..63
#define OFF_W1T   8192     // 20*128 = 2560, layout [i][j]: (W1[j][i]) along j contiguous
#define OFF_W3T   10752    // 64*32  = 2048, layout [k][m]: (W3[m][k]) along m contiguous
#define OFF_B1    12800    // 128
#define OFF_B2    12928    // 64
#define OFF_B3    12992    // 32
#define OFF_W4    13024    // 32
#define OFF_WIH   13056    // 32 (8x4)
#define OFF_WHH   13088    // 16 (8x2)
#define OFF_BIAS  13104    // 8  (b_ih + b_hh)
#define OFF_B4    13112    // 1
#define SMEM_FLOATS 13120
#define SMEM_BYTES  (SMEM_FLOATS * 4)

__global__ void __launch_bounds__(NTHREADS, 3)
lstm_mlp_fused_kernel(const float* __restrict__ x,
                      const float* __restrict__ W_ih, const float* __restrict__ W_hh,
                      const float* __restrict__ b_ih, const float* __restrict__ b_hh,
                      const float* __restrict__ W1, const float* __restrict__ b1,
                      const float* __restrict__ W2, const float* __restrict__ b2,
                      const float* __restrict__ W3, const float* __restrict__ b3,
                      const float* __restrict__ W4, const float* __restrict__ b4,
                      float* __restrict__ out, int n)
{
    extern __shared__ float sm[];
    float* sW2t  = sm + OFF_W2T;
    float* sW1t  = sm + OFF_W1T;
    float* sW3t  = sm + OFF_W3T;
    float* sB1   = sm + OFF_B1;
    float* sB2   = sm + OFF_B2;
    float* sB3   = sm + OFF_B3;
    float* sW4   = sm + OFF_W4;
    float* sWih  = sm + OFF_WIH;
    float* sWhh  = sm + OFF_WHH;
    float* sBias = sm + OFF_BIAS;
    float* sB4   = sm + OFF_B4;

    const int tid = threadIdx.x;

    // ---- stage + transpose weights into SMEM (once per CTA) ----
    for (int idx = tid; idx < 20 * 128; idx += NTHREADS) {
        int i = idx >> 7, j = idx & 127;           // sW1t[i*128 + j] = W1[j][i]
        sW1t[idx] = W1[j * 20 + i];
    }
    for (int idx = tid; idx < 64 * 128; idx += NTHREADS) {
        int j = idx >> 6, k = idx & 63;            // sW2t[j*64 + k] = W2[k][j]
        sW2t[idx] = W2[k * 128 + j];
    }
    for (int idx = tid; idx < 64 * 32; idx += NTHREADS) {
        int k = idx >> 5, m = idx & 31;            // sW3t[k*32 + m] = W3[m][k]
        sW3t[idx] = W3[m * 64 + k];
    }
    if (tid < 128) sB1[tid] = b1[tid];
    if (tid < 64)  sB2[tid] = b2[tid];
    if (tid < 32)  { sB3[tid] = b3[tid]; sW4[tid] = W4[tid]; }
    if (tid < 32)  sWih[tid] = W_ih[tid];
    if (tid < 16)  sWhh[tid] = W_hh[tid];
    if (tid < 8)   sBias[tid] = b_ih[tid] + b_hh[tid];
    if (tid == 0)  sB4[0] = b4[0];
    __syncthreads();

    const int stride = gridDim.x * NTHREADS;
    for (int b = blockIdx.x * NTHREADS + tid; b < n; b += stride) {
        // ================= LSTM (scalar fp32) =================
        float h0 = 0.f, h1 = 0.f, c0 = 0.f, c1 = 0.f;
        u64 hb[20];                                  // packed (h,h) broadcasts
        const float* xb = x + (size_t)b * 40;        // [T=10][I=4]
#pragma unroll
        for (int t = 0; t < 10; t++) {
            float4 xt = *reinterpret_cast<const float4*>(xb + t * 4);
            float g[8];
#pragma unroll
            for (int gi = 0; gi < 8; gi++) {
                float a = sBias[gi];
                a = fmaf(xt.x, sWih[gi * 4 + 0], a);
                a = fmaf(xt.y, sWih[gi * 4 + 1], a);
                a = fmaf(xt.z, sWih[gi * 4 + 2], a);
                a = fmaf(xt.w, sWih[gi * 4 + 3], a);
                a = fmaf(h0, sWhh[gi * 2 + 0], a);
                a = fmaf(h1, sWhh[gi * 2 + 1], a);
                g[gi] = a;
            }
            float i0 = sigf(g[0]),      i1 = sigf(g[1]);
            float f0 = sigf(g[2]),      f1 = sigf(g[3]);
            float g0 = tanhfast(g[4]),  g1 = tanhfast(g[5]);
            float o0 = sigf(g[6]),      o1 = sigf(g[7]);
            c0 = fmaf(f0, c0, i0 * g0);
            c1 = fmaf(f1, c1, i1 * g1);
            h0 = o0 * tanhfast(c0);
            h1 = o1 * tanhfast(c1);
            hb[2 * t]     = bcast(h0);
            hb[2 * t + 1] = bcast(h1);
        }

        // ============ MLP layer1(20->128) fused into layer2(128->64) ============
        // Process layer-1 neurons in QUADS so every weight LDS is a 128-bit
        // broadcast (1 wavefront -> 2 fma2). acc2: 32 packed layer-2 pairs.
        u64 acc2[32];
#pragma unroll
        for (int k2 = 0; k2 < 16; k2++) {
            ulonglong2 bb = lds128(&sB2[4 * k2]);
            acc2[2 * k2]     = bb.x;
            acc2[2 * k2 + 1] = bb.y;
        }

#pragma unroll 1
        for (int jq = 0; jq < 32; jq++) {            // neurons 4jq .. 4jq+3
            ulonglong2 ab = lds128(&sB1[4 * jq]);
            u64 aA = ab.x, aB = ab.y;
            const float* w1p = &sW1t[4 * jq];
#pragma unroll
            for (int i = 0; i < 20; i++) {
                ulonglong2 w = lds128(w1p + i * 128);
                aA = fma2(hb[i], w.x, aA);
                aB = fma2(hb[i], w.y, aB);
            }
            float a0, a1v, a2, a3;
            unpack2(aA, a0, a1v);
            unpack2(aB, a2, a3);
            a0  = fmaxf(a0, 0.f);
            a1v = fmaxf(a1v, 0.f);
            a2  = fmaxf(a2, 0.f);
            a3  = fmaxf(a3, 0.f);
            u64 v0 = bcast(a0), v1 = bcast(a1v), v2 = bcast(a2), v3 = bcast(a3);

            const float* w2p = &sW2t[(4 * jq) * 64];
            // row r: 64 floats = 16 LDS.128, each feeding 2 fma2
#pragma unroll
            for (int k = 0; k < 16; k++) {
                ulonglong2 w = lds128(w2p + 4 * k);
                acc2[2 * k]     = fma2(v0, w.x, acc2[2 * k]);
                acc2[2 * k + 1] = fma2(v0, w.y, acc2[2 * k + 1]);
            }
#pragma unroll
            for (int k = 0; k < 16; k++) {
                ulonglong2 w = lds128(w2p + 64 + 4 * k);
                acc2[2 * k]     = fma2(v1, w.x, acc2[2 * k]);
                acc2[2 * k + 1] = fma2(v1, w.y, acc2[2 * k + 1]);
            }
#pragma unroll
            for (int k = 0; k < 16; k++) {
                ulonglong2 w = lds128(w2p + 128 + 4 * k);
                acc2[2 * k]     = fma2(v2, w.x, acc2[2 * k]);
                acc2[2 * k + 1] = fma2(v2, w.y, acc2[2 * k + 1]);
            }
#pragma unroll
            for (int k = 0; k < 16; k++) {
                ulonglong2 w = lds128(w2p + 192 + 4 * k);
                acc2[2 * k]     = fma2(v3, w.x, acc2[2 * k]);
                acc2[2 * k + 1] = fma2(v3, w.y, acc2[2 * k + 1]);
            }
        }

        // ============ layer3 (64->32), incremental from acc2 ============
        u64 acc3[16];
#pragma unroll
        for (int m = 0; m < 8; m++) {
            ulonglong2 bb = lds128(&sB3[4 * m]);
            acc3[2 * m]     = bb.x;
            acc3[2 * m + 1] = bb.y;
        }
#pragma unroll 1
        for (int kp = 0; kp < 32; kp++) {
            float s0, s1;
            unpack2(acc2[kp], s0, s1);
            s0 = fmaxf(s0, 0.f);
            s1 = fmaxf(s1, 0.f);
            u64 u0 = bcast(s0), u1 = bcast(s1);
            const float* w3p = &sW3t[(2 * kp) * 32];
#pragma unroll
            for (int m = 0; m < 8; m++) {
                ulonglong2 w = lds128(w3p + 4 * m);
                acc3[2 * m]     = fma2(u0, w.x, acc3[2 * m]);
                acc3[2 * m + 1] = fma2(u0, w.y, acc3[2 * m + 1]);
            }
#pragma unroll
            for (int m = 0; m < 8; m++) {
                ulonglong2 w = lds128(w3p + 32 + 4 * m);
                acc3[2 * m]     = fma2(u1, w.x, acc3[2 * m]);
                acc3[2 * m + 1] = fma2(u1, w.y, acc3[2 * m + 1]);
            }
        }

        // ============ layer4 (32->1), scalar ============
        float o = sB4[0];
#pragma unroll
        for (int mp = 0; mp < 16; mp++) {
            float t0, t1;
            unpack2(acc3[mp], t0, t1);
            t0 = fmaxf(t0, 0.f);
            t1 = fmaxf(t1, 0.f);
            o = fmaf(t0, sW4[2 * mp], o);
            o = fmaf(t1, sW4[2 * mp + 1], o);
        }
        out[b] = o;
    }
}

extern "C" void kernel_launch(void* const* d_in, const int* in_sizes, int n_in,
                              void* d_out, int out_size)
{
    const float* x    = (const float*)d_in[0];
    const float* W_ih = (const float*)d_in[1];
    const float* W_hh = (const float*)d_in[2];
    const float* b_ih = (const float*)d_in[3];
    const float* b_hh = (const float*)d_in[4];
    const float* W1   = (const float*)d_in[5];
    const float* b1   = (const float*)d_in[6];
    const float* W2   = (const float*)d_in[7];
    const float* b2   = (const float*)d_in[8];
    const float* W3   = (const float*)d_in[9];
    const float* b3   = (const float*)d_in[10];
    const float* W4   = (const float*)d_in[11];
    const float* b4   = (const float*)d_in[12];
    float* out = (float*)d_out;

    static bool attr_set = false;
    if (!attr_set) {
        cudaFuncSetAttribute(lstm_mlp_fused_kernel,
                             cudaFuncAttributeMaxDynamicSharedMemorySize, SMEM_BYTES);
        attr_set = true;
    }

    lstm_mlp_fused_kernel<<<NBLOCKS, NTHREADS, SMEM_BYTES>>>(
        x, W_ih, W_hh, b_ih, b_hh, W1, b1, W2, b2, W3, b3, W4, b4,
        out, out_size);
}

// round 3
// speedup vs baseline: 1.7988x; 1.7988x over previous
#include <cuda_runtime.h>

typedef unsigned long long u64;

#define NTHREADS 128
#define NBLOCKS  (148 * 2)

// ---------------- packed f32x2 helpers (sm_103a) ----------------
__device__ __forceinline__ u64 fma2(u64 a, u64 b, u64 c) {
    u64 d;
    asm("fma.rn.f32x2 %0, %1, %2, %3;" : "=l"(d) : "l"(a), "l"(b), "l"(c));
    return d;
}
__device__ __forceinline__ u64 pack2(float lo, float hi) {
    u64 d;
    asm("mov.b64 %0, {%1, %2};" : "=l"(d) : "f"(lo), "f"(hi));
    return d;
}
__device__ __forceinline__ void unpack2(u64 v, float& lo, float& hi) {
    asm("mov.b64 {%0, %1}, %2;" : "=f"(lo), "=f"(hi) : "l"(v));
}
__device__ __forceinline__ u64 bcast(float x) { return pack2(x, x); }
__device__ __forceinline__ u64 lds64(const float* p) {
    return *reinterpret_cast<const u64*>(p);
}

// ---------------- fast activations (accurate to ~1e-6 rel) ----------------
__device__ __forceinline__ float sigf(float x) {
    float e = __expf(-x);
    return __fdividef(1.0f, 1.0f + e);
}
__device__ __forceinline__ float tanhfast(float x) {
    float e = __expf(-2.0f * x);
    return __fdividef(2.0f, 1.0f + e) - 1.0f;
}

// SMEM layout (floats): offsets even (8B-aligned for LDS.64)
#define OFF_W2T   0        // 64*128 = 8192, [j][k]: (W2[k][j],W2[k+1][j]) contiguous
#define OFF_W1T   8192     // 20*128 = 2560, [i][j]
#define OFF_W3T   10752    // 64*32  = 2048, [k][m]
#define OFF_B1    12800    // 128
#define OFF_B2    12928    // 64
#define OFF_B3    12992    // 32
#define OFF_W4    13024    // 32
#define OFF_WIH   13056    // 32 (8x4)
#define OFF_WHH   13088    // 16 (8x2)
#define OFF_BIAS  13104    // 8  (b_ih + b_hh)
#define OFF_B4    13112    // 1
#define SMEM_FLOATS 13120
#define SMEM_BYTES  (SMEM_FLOATS * 4)

__global__ void __launch_bounds__(NTHREADS, 2)
lstm_mlp_fused_kernel(const float* __restrict__ x,
                      const float* __restrict__ W_ih, const float* __restrict__ W_hh,
                      const float* __restrict__ b_ih, const float* __restrict__ b_hh,
                      const float* __restrict__ W1, const float* __restrict__ b1,
                      const float* __restrict__ W2, const float* __restrict__ b2,
                      const float* __restrict__ W3, const float* __restrict__ b3,
                      const float* __restrict__ W4, const float* __restrict__ b4,
                      float* __restrict__ out, int n)
{
    extern __shared__ float sm[];
    float* sW2t  = sm + OFF_W2T;
    float* sW1t  = sm + OFF_W1T;
    float* sW3t  = sm + OFF_W3T;
    float* sB1   = sm + OFF_B1;
    float* sB2   = sm + OFF_B2;
    float* sB3   = sm + OFF_B3;
    float* sW4   = sm + OFF_W4;
    float* sWih  = sm + OFF_WIH;
    float* sWhh  = sm + OFF_WHH;
    float* sBias = sm + OFF_BIAS;
    float* sB4   = sm + OFF_B4;

    const int tid = threadIdx.x;

    // ---- stage + transpose weights into SMEM (once per CTA) ----
    for (int idx = tid; idx < 20 * 128; idx += NTHREADS) {
        int i = idx >> 7, j = idx & 127;
        sW1t[idx] = W1[j * 20 + i];
    }
    for (int idx = tid; idx < 64 * 128; idx += NTHREADS) {
        int j = idx >> 6, k = idx & 63;
        sW2t[idx] = W2[k * 128 + j];
    }
    for (int idx = tid; idx < 64 * 32; idx += NTHREADS) {
        int k = idx >> 5, m = idx & 31;
        sW3t[idx] = W3[m * 64 + k];
    }
    if (tid < 128) sB1[tid] = b1[tid];
    if (tid < 64)  sB2[tid] = b2[tid];
    if (tid < 32)  { sB3[tid] = b3[tid]; sW4[tid] = W4[tid]; }
    if (tid < 32)  sWih[tid] = W_ih[tid];
    if (tid < 16)  sWhh[tid] = W_hh[tid];
    if (tid < 8)   sBias[tid] = b_ih[tid] + b_hh[tid];
    if (tid == 0)  sB4[0] = b4[0];
    __syncthreads();

    // Hoist LSTM weights to registers (dead before MLP register peak)
    float rwih[32], rwhh[16], rbias[8];
#pragma unroll
    for (int i = 0; i < 32; i++) rwih[i] = sWih[i];
#pragma unroll
    for (int i = 0; i < 16; i++) rwhh[i] = sWhh[i];
#pragma unroll
    for (int i = 0; i < 8; i++)  rbias[i] = sBias[i];

    const int half = (n + 1) >> 1;
    const int stride = gridDim.x * NTHREADS;
    for (int p = blockIdx.x * NTHREADS + tid; p < half; p += stride) {
        const int b0 = p;
        const int b1 = p + half;
        const bool has_b1 = (b1 < n);
        const int b1c = has_b1 ? b1 : b0;

        // ================= LSTM for both elements (scalar fp32) =================
        float h0a = 0.f, h1a = 0.f, c0a = 0.f, c1a = 0.f;
        float h0b = 0.f, h1b = 0.f, c0b = 0.f, c1b = 0.f;
        u64 hb0[20], hb1[20];
        const float* xa = x + (size_t)b0 * 40;
        const float* xb = x + (size_t)b1c * 40;
#pragma unroll
        for (int t = 0; t < 10; t++) {
            float4 xta = *reinterpret_cast<const float4*>(xa + t * 4);
            float4 xtb = *reinterpret_cast<const float4*>(xb + t * 4);
            float ga[8], gb[8];
#pragma unroll
            for (int gi = 0; gi < 8; gi++) {
                float a = rbias[gi];
                a = fmaf(xta.x, rwih[gi * 4 + 0], a);
                a = fmaf(xta.y, rwih[gi * 4 + 1], a);
                a = fmaf(xta.z, rwih[gi * 4 + 2], a);
                a = fmaf(xta.w, rwih[gi * 4 + 3], a);
                a = fmaf(h0a, rwhh[gi * 2 + 0], a);
                a = fmaf(h1a, rwhh[gi * 2 + 1], a);
                ga[gi] = a;
                float bvv = rbias[gi];
                bvv = fmaf(xtb.x, rwih[gi * 4 + 0], bvv);
                bvv = fmaf(xtb.y, rwih[gi * 4 + 1], bvv);
                bvv = fmaf(xtb.z, rwih[gi * 4 + 2], bvv);
                bvv = fmaf(xtb.w, rwih[gi * 4 + 3], bvv);
                bvv = fmaf(h0b, rwhh[gi * 2 + 0], bvv);
                bvv = fmaf(h1b, rwhh[gi * 2 + 1], bvv);
                gb[gi] = bvv;
            }
            float i0a = sigf(ga[0]),     i1a = sigf(ga[1]);
            float f0a = sigf(ga[2]),     f1a = sigf(ga[3]);
            float g0a = tanhfast(ga[4]), g1a = tanhfast(ga[5]);
            float o0a = sigf(ga[6]),     o1a = sigf(ga[7]);
            float i0b = sigf(gb[0]),     i1b = sigf(gb[1]);
            float f0b = sigf(gb[2]),     f1b = sigf(gb[3]);
            float g0b = tanhfast(gb[4]), g1b = tanhfast(gb[5]);
            float o0b = sigf(gb[6]),     o1b = sigf(gb[7]);
            c0a = fmaf(f0a, c0a, i0a * g0a);
            c1a = fmaf(f1a, c1a, i1a * g1a);
            c0b = fmaf(f0b, c0b, i0b * g0b);
            c1b = fmaf(f1b, c1b, i1b * g1b);
            h0a = o0a * tanhfast(c0a);
            h1a = o1a * tanhfast(c1a);
            h0b = o0b * tanhfast(c0b);
            h1b = o1b * tanhfast(c1b);
            hb0[2 * t]     = bcast(h0a);
            hb0[2 * t + 1] = bcast(h1a);
            hb1[2 * t]     = bcast(h0b);
            hb1[2 * t + 1] = bcast(h1b);
        }

        // ============ MLP layer1(20->128) fused into layer2(128->64) ============
        // Lanes of f32x2 = neuron pairs; one weight LDS feeds BOTH elements.
        u64 acc2a[32], acc2b[32];
#pragma unroll
        for (int k2 = 0; k2 < 32; k2++) {
            u64 bb = lds64(&sB2[2 * k2]);
            acc2a[k2] = bb;
            acc2b[k2] = bb;
        }

#pragma unroll 1
        for (int jp = 0; jp < 64; jp++) {           // neuron pair (2jp, 2jp+1)
            u64 binit = lds64(&sB1[2 * jp]);
            u64 aA = binit, aB = binit;
            const float* w1p = &sW1t[2 * jp];
#pragma unroll
            for (int i = 0; i < 20; i++) {
                u64 w = lds64(w1p + i * 128);
                aA = fma2(hb0[i], w, aA);
                aB = fma2(hb1[i], w, aB);
            }
            float a0a, a1a, a0b, a1b;
            unpack2(aA, a0a, a1a);
            unpack2(aB, a0b, a1b);
            u64 v0a = bcast(fmaxf(a0a, 0.f));
            u64 v1a = bcast(fmaxf(a1a, 0.f));
            u64 v0b = bcast(fmaxf(a0b, 0.f));
            u64 v1b = bcast(fmaxf(a1b, 0.f));

            const float* w0 = &sW2t[(2 * jp) * 64];
            const float* w1 = w0 + 64;
#pragma unroll
            for (int k = 0; k < 32; k++) {
                u64 w = lds64(w0 + 2 * k);
                acc2a[k] = fma2(v0a, w, acc2a[k]);
                acc2b[k] = fma2(v0b, w, acc2b[k]);
            }
#pragma unroll
            for (int k = 0; k < 32; k++) {
                u64 w = lds64(w1 + 2 * k);
                acc2a[k] = fma2(v1a, w, acc2a[k]);
                acc2b[k] = fma2(v1b, w, acc2b[k]);
            }
        }

        // ============ layer3 (64->32) ============
        u64 acc3a[16], acc3b[16];
#pragma unroll
        for (int m = 0; m < 16; m++) {
            u64 bb = lds64(&sB3[2 * m]);
            acc3a[m] = bb;
            acc3b[m] = bb;
        }
#pragma unroll 1
        for (int kp = 0; kp < 32; kp++) {
            float s0a, s1a, s0b, s1b;
            unpack2(acc2a[kp], s0a, s1a);
            unpack2(acc2b[kp], s0b, s1b);
            u64 u0a = bcast(fmaxf(s0a, 0.f));
            u64 u1a = bcast(fmaxf(s1a, 0.f));
            u64 u0b = bcast(fmaxf(s0b, 0.f));
            u64 u1b = bcast(fmaxf(s1b, 0.f));
            const float* w0 = &sW3t[(2 * kp) * 32];
            const float* w1 = w0 + 32;
#pragma unroll
            for (int m = 0; m < 16; m++) {
                u64 w = lds64(w0 + 2 * m);
                acc3a[m] = fma2(u0a, w, acc3a[m]);
                acc3b[m] = fma2(u0b, w, acc3b[m]);
            }
#pragma unroll
            for (int m = 0; m < 16; m++) {
                u64 w = lds64(w1 + 2 * m);
                acc3a[m] = fma2(u1a, w, acc3a[m]);
                acc3b[m] = fma2(u1b, w, acc3b[m]);
            }
        }

        // ============ layer4 (32->1), scalar ============
        float oa = sB4[0];
        float ob = oa;
#pragma unroll
        for (int mp = 0; mp < 16; mp++) {
            u64 wp = lds64(&sW4[2 * mp]);
            float w0s, w1s;
            unpack2(wp, w0s, w1s);
            float t0a, t1a, t0b, t1b;
            unpack2(acc3a[mp], t0a, t1a);
            unpack2(acc3b[mp], t0b, t1b);
            oa = fmaf(fmaxf(t0a, 0.f), w0s, oa);
            oa = fmaf(fmaxf(t1a, 0.f), w1s, oa);
            ob = fmaf(fmaxf(t0b, 0.f), w0s, ob);
            ob = fmaf(fmaxf(t1b, 0.f), w1s, ob);
        }
        out[b0] = oa;
        if (has_b1) out[b1] = ob;
    }
}

extern "C" void kernel_launch(void* const* d_in, const int* in_sizes, int n_in,
                              void* d_out, int out_size)
{
    const float* x    = (const float*)d_in[0];
    const float* W_ih = (const float*)d_in[1];
    const float* W_hh = (const float*)d_in[2];
    const float* b_ih = (const float*)d_in[3];
    const float* b_hh = (const float*)d_in[4];
    const float* W1   = (const float*)d_in[5];
    const float* b1   = (const float*)d_in[6];
    const float* W2   = (const float*)d_in[7];
    const float* b2   = (const float*)d_in[8];
    const float* W3   = (const float*)d_in[9];
    const float* b3   = (const float*)d_in[10];
    const float* W4   = (const float*)d_in[11];
    const float* b4   = (const float*)d_in[12];
    float* out = (float*)d_out;

    static bool attr_set = false;
    if (!attr_set) {
        cudaFuncSetAttribute(lstm_mlp_fused_kernel,
                             cudaFuncAttributeMaxDynamicSharedMemorySize, SMEM_BYTES);
        attr_set = true;
    }

    lstm_mlp_fused_kernel<<<NBLOCKS, NTHREADS, SMEM_BYTES>>>(
        x, W_ih, W_hh, b_ih, b_hh, W1, b1, W2, b2, W3, b3, W4, b4,
        out, out_size);
}